// round 6
// baseline (speedup 1.0000x reference)
#include <cuda_runtime.h>
#include <math.h>

// Problem constants
#define N_TOK 65536
#define D_IN  1024
#define H_DIM 512
#define HH    256          // H/2
#define R_REG 16
#define M_PER (N_TOK / R_REG)   // 4096
#define SPLITS 64

// ---------------- static device scratch (no allocations allowed) ----------------
__device__ float g_region_emb[N_TOK * H_DIM];            // 128 MiB
__device__ float g_scores[N_TOK];
__device__ float g_rmax[R_REG];
__device__ float g_rsum[R_REG];
__device__ float g_partial[R_REG * SPLITS * H_DIM];      // 2 MiB
__device__ float g_region_features[R_REG * H_DIM];
__device__ float g_slide_emb[R_REG * H_DIM];
__device__ float g_sa[R_REG];

__device__ __forceinline__ float gelu_f(float x) {
    // exact-erf GELU (matches torch nn.GELU default / jax approximate=False)
    return 0.5f * x * (1.0f + erff(x * 0.70710678118654752440f));
}

// =================================================================================
// K1: region_emb = gelu(E @ W1 + b1)
// E: (65536 x 1024) row-major, W1: (1024 x 512) row-major
// Tile: BM=128, BN=128, BK=16, 256 threads, 8x8 per-thread microtile,
// register prefetch of next tile to hide gmem latency.
// =================================================================================
__global__ __launch_bounds__(256, 2)
void k1_gemm_gelu(const float* __restrict__ A, const float* __restrict__ W,
                  const float* __restrict__ bias)
{
    const int BM = 128, BN = 128, BK = 16;
    __shared__ float As[BK][BM];   // transposed A tile: [k][m]
    __shared__ float Bs[BK][BN];   // [k][n]

    const int tid = threadIdx.x;
    const int bx = blockIdx.x;     // column block (0..3)
    const int by = blockIdx.y;     // row block    (0..511)
    const int tr = tid >> 4;       // 0..15 -> rows tr*8 .. tr*8+7
    const int tc = tid & 15;       // 0..15 -> cols tc*4..+3 and tc*4+64..+3

    // A tile: 128x16 = 2048 floats = 2 float4 per thread
    const int lin0 = tid * 4;
    const int lin1 = 1024 + tid * 4;
    const int ar0 = lin0 >> 4, ak0 = lin0 & 15;
    const int ar1 = lin1 >> 4, ak1 = lin1 & 15;
    const float* Ag0 = A + (long)(by * BM + ar0) * D_IN + ak0;
    const float* Ag1 = A + (long)(by * BM + ar1) * D_IN + ak1;

    // B tile: 16x128 = 2048 floats = 2 float4 per thread
    const int br0 = lin0 >> 7, bc0 = lin0 & 127;
    const int br1 = lin1 >> 7, bc1 = lin1 & 127;
    const float* Bg0 = W + (long)br0 * H_DIM + bx * BN + bc0;
    const float* Bg1 = W + (long)br1 * H_DIM + bx * BN + bc1;

    float4 pa0 = *(const float4*)(Ag0);
    float4 pa1 = *(const float4*)(Ag1);
    float4 pb0 = *(const float4*)(Bg0);
    float4 pb1 = *(const float4*)(Bg1);

    float acc[8][8] = {};

    for (int k0 = 0; k0 < D_IN; k0 += BK) {
        // store prefetched tiles (A transposed, scalar stores)
        As[ak0 + 0][ar0] = pa0.x; As[ak0 + 1][ar0] = pa0.y;
        As[ak0 + 2][ar0] = pa0.z; As[ak0 + 3][ar0] = pa0.w;
        As[ak1 + 0][ar1] = pa1.x; As[ak1 + 1][ar1] = pa1.y;
        As[ak1 + 2][ar1] = pa1.z; As[ak1 + 3][ar1] = pa1.w;
        *(float4*)&Bs[br0][bc0] = pb0;
        *(float4*)&Bs[br1][bc1] = pb1;
        __syncthreads();

        if (k0 + BK < D_IN) {
            pa0 = *(const float4*)(Ag0 + k0 + BK);
            pa1 = *(const float4*)(Ag1 + k0 + BK);
            pb0 = *(const float4*)(Bg0 + (long)(k0 + BK) * H_DIM);
            pb1 = *(const float4*)(Bg1 + (long)(k0 + BK) * H_DIM);
        }

        #pragma unroll
        for (int k = 0; k < BK; k++) {
            float a[8], b[8];
            *(float4*)&a[0] = *(const float4*)&As[k][tr * 8];
            *(float4*)&a[4] = *(const float4*)&As[k][tr * 8 + 4];
            *(float4*)&b[0] = *(const float4*)&Bs[k][tc * 4];
            *(float4*)&b[4] = *(const float4*)&Bs[k][tc * 4 + 64];
            #pragma unroll
            for (int i = 0; i < 8; i++)
                #pragma unroll
                for (int j = 0; j < 8; j++)
                    acc[i][j] = fmaf(a[i], b[j], acc[i][j]);
        }
        __syncthreads();
    }

    // epilogue: bias + gelu, float4 stores
    const int cb = bx * BN + tc * 4;
    float bv[8];
    #pragma unroll
    for (int j = 0; j < 4; j++) { bv[j] = bias[cb + j]; bv[4 + j] = bias[cb + 64 + j]; }

    #pragma unroll
    for (int i = 0; i < 8; i++) {
        const int row = by * BM + tr * 8 + i;
        float* o = g_region_emb + (long)row * H_DIM;
        float4 v;
        v.x = gelu_f(acc[i][0] + bv[0]);
        v.y = gelu_f(acc[i][1] + bv[1]);
        v.z = gelu_f(acc[i][2] + bv[2]);
        v.w = gelu_f(acc[i][3] + bv[3]);
        *(float4*)(o + cb) = v;
        v.x = gelu_f(acc[i][4] + bv[4]);
        v.y = gelu_f(acc[i][5] + bv[5]);
        v.z = gelu_f(acc[i][6] + bv[6]);
        v.w = gelu_f(acc[i][7] + bv[7]);
        *(float4*)(o + cb + 64) = v;
    }
}

// =================================================================================
// K2: scores[n] = tanh(region_emb[n,:] @ Wa1 + ba1) @ Wa2 + ba2
// GEMM tile covers the FULL 256-wide Wa1 so the tanh+Wa2 contraction fuses into
// the epilogue (65536x256 intermediate never materialized).
// BM=64, BN=256, BK=16, 256 threads, 8x8 microtile. warp == thread-row group.
// =================================================================================
__global__ __launch_bounds__(256, 2)
void k2_scores(const float* __restrict__ Wa1, const float* __restrict__ ba1,
               const float* __restrict__ Wa2, const float* __restrict__ ba2)
{
    const int BM = 64, BK = 16;
    __shared__ float As[BK][BM];     // transposed
    __shared__ float Bs[BK][256];

    const int tid = threadIdx.x;
    const int bx = blockIdx.x;       // 0..1023 (row block of 64 tokens)
    const int tr = tid >> 5;         // 0..7  (warp id)
    const int tc = tid & 31;         // lane

    // A tile: 64x16 = 1024 floats -> 1 float4/thread
    const int lin = tid * 4;
    const int ar = lin >> 4, ak = lin & 15;
    const float* Ag = g_region_emb + (long)(bx * BM + ar) * H_DIM + ak;

    float4 pa = *(const float4*)Ag;
    float4 pb[4];
    #pragma unroll
    for (int i = 0; i < 4; i++) {
        const int l = i * 1024 + tid * 4;
        pb[i] = *(const float4*)(Wa1 + (long)(l >> 8) * HH + (l & 255));
    }

    float acc[8][8] = {};

    for (int k0 = 0; k0 < H_DIM; k0 += BK) {
        As[ak + 0][ar] = pa.x; As[ak + 1][ar] = pa.y;
        As[ak + 2][ar] = pa.z; As[ak + 3][ar] = pa.w;
        #pragma unroll
        for (int i = 0; i < 4; i++) {
            const int l = i * 1024 + tid * 4;
            *(float4*)&Bs[l >> 8][l & 255] = pb[i];
        }
        __syncthreads();

        if (k0 + BK < H_DIM) {
            pa = *(const float4*)(Ag + k0 + BK);
            #pragma unroll
            for (int i = 0; i < 4; i++) {
                const int l = i * 1024 + tid * 4;
                pb[i] = *(const float4*)(Wa1 + (long)((l >> 8) + k0 + BK) * HH + (l & 255));
            }
        }

        #pragma unroll
        for (int k = 0; k < BK; k++) {
            float a[8], b[8];
            *(float4*)&a[0] = *(const float4*)&As[k][tr * 8];
            *(float4*)&a[4] = *(const float4*)&As[k][tr * 8 + 4];
            *(float4*)&b[0] = *(const float4*)&Bs[k][tc * 4];
            *(float4*)&b[4] = *(const float4*)&Bs[k][tc * 4 + 128];
            #pragma unroll
            for (int i = 0; i < 8; i++)
                #pragma unroll
                for (int j = 0; j < 8; j++)
                    acc[i][j] = fmaf(a[i], b[j], acc[i][j]);
        }
        __syncthreads();
    }

    // epilogue: tanh, weight by Wa2, per-row reduce (this thread's 8 cols),
    // then warp shuffle-reduce across the 32 column groups (= lanes).
    const int c0 = tc * 4, c1 = tc * 4 + 128;
    float b1r[8], w2r[8];
    #pragma unroll
    for (int j = 0; j < 4; j++) {
        b1r[j]     = ba1[c0 + j];  w2r[j]     = Wa2[c0 + j];
        b1r[4 + j] = ba1[c1 + j];  w2r[4 + j] = Wa2[c1 + j];
    }

    float p[8];
    #pragma unroll
    for (int i = 0; i < 8; i++) {
        float s = 0.f;
        #pragma unroll
        for (int j = 0; j < 8; j++)
            s += tanhf(acc[i][j] + b1r[j]) * w2r[j];
        p[i] = s;
    }
    #pragma unroll
    for (int off = 16; off > 0; off >>= 1)
        #pragma unroll
        for (int i = 0; i < 8; i++)
            p[i] += __shfl_down_sync(0xffffffffu, p[i], off);

    if (tc == 0) {
        const float bb = ba2[0];
        #pragma unroll
        for (int i = 0; i < 8; i++)
            g_scores[bx * BM + tr * 8 + i] = p[i] + bb;
    }
}

// =================================================================================
// K3a: per-region max and sum(exp(score-max)).  Region r owns tokens m*16 + r.
// =================================================================================
__global__ void k3a_region_stats()
{
    __shared__ float red[256];
    const int r = blockIdx.x, tid = threadIdx.x;

    float mx = -1e30f;
    for (int m = tid; m < M_PER; m += 256)
        mx = fmaxf(mx, g_scores[m * R_REG + r]);
    red[tid] = mx; __syncthreads();
    for (int s = 128; s > 0; s >>= 1) {
        if (tid < s) red[tid] = fmaxf(red[tid], red[tid + s]);
        __syncthreads();
    }
    mx = red[0];
    __syncthreads();

    float sum = 0.f;
    for (int m = tid; m < M_PER; m += 256)
        sum += expf(g_scores[m * R_REG + r] - mx);
    red[tid] = sum; __syncthreads();
    for (int s = 128; s > 0; s >>= 1) {
        if (tid < s) red[tid] += red[tid + s];
        __syncthreads();
    }
    if (tid == 0) { g_rmax[r] = mx; g_rsum[r] = red[0]; }
}

// =================================================================================
// K3b: deterministic split partial weighted sums: each (split,region) block sums
// 64 token rows weighted by exp(score-max). No atomics -> bitwise deterministic.
// =================================================================================
__global__ void k3b_weighted_partial()
{
    const int s = blockIdx.x, r = blockIdx.y, tid = threadIdx.x;
    const float rmax = g_rmax[r];
    const int m0 = s * (M_PER / SPLITS);   // *64
    float a0 = 0.f, a1 = 0.f;
    #pragma unroll 4
    for (int mm = 0; mm < M_PER / SPLITS; mm++) {
        const int n = (m0 + mm) * R_REG + r;
        const float w = expf(g_scores[n] - rmax);
        const float* row = g_region_emb + (long)n * H_DIM;
        a0 += w * row[tid];
        a1 += w * row[tid + 256];
    }
    float* o = g_partial + (long)(r * SPLITS + s) * H_DIM;
    o[tid] = a0; o[tid + 256] = a1;
}

// K3c: reduce partials -> region_features (divide by sumexp)
__global__ void k3c_reduce_rf()
{
    const int r = blockIdx.x, h = threadIdx.x;   // 512 threads
    float a = 0.f;
    for (int s = 0; s < SPLITS; s++)
        a += g_partial[(long)(r * SPLITS + s) * H_DIM + h];
    g_region_features[r * H_DIM + h] = a / g_rsum[r];
}

// =================================================================================
// K4a: slide_emb = gelu(region_features @ Ws + bs)   (16 x 512)
// =================================================================================
__global__ void k4a_slide_emb(const float* __restrict__ Ws, const float* __restrict__ bs)
{
    __shared__ float rf[H_DIM];
    const int r = blockIdx.x, h = threadIdx.x;   // 512 threads
    rf[h] = g_region_features[r * H_DIM + h];
    __syncthreads();
    float a = 0.f;
    #pragma unroll 4
    for (int k = 0; k < H_DIM; k++)
        a += rf[k] * Ws[k * H_DIM + h];
    g_slide_emb[r * H_DIM + h] = gelu_f(a + bs[h]);
}

// K4b: slide attention score per region
__global__ void k4b_slide_attn(const float* __restrict__ Wsa1, const float* __restrict__ bsa1,
                               const float* __restrict__ Wsa2, const float* __restrict__ bsa2)
{
    __shared__ float se[H_DIM];
    __shared__ float red[256];
    const int r = blockIdx.x, j = threadIdx.x;   // 256 threads
    se[j] = g_slide_emb[r * H_DIM + j];
    se[j + 256] = g_slide_emb[r * H_DIM + j + 256];
    __syncthreads();
    float a = 0.f;
    #pragma unroll 4
    for (int h = 0; h < H_DIM; h++)
        a += se[h] * Wsa1[h * HH + j];
    red[j] = tanhf(a + bsa1[j]) * Wsa2[j];
    __syncthreads();
    for (int s = 128; s > 0; s >>= 1) {
        if (j < s) red[j] += red[j + s];
        __syncthreads();
    }
    if (j == 0) g_sa[r] = red[0] + bsa2[0];
}

// K4c: softmax over regions, slide_rep, classifier -> logits
__global__ void k4c_classify(const float* __restrict__ Wc1, const float* __restrict__ bc1,
                             const float* __restrict__ Wc2, const float* __restrict__ bc2,
                             float* __restrict__ out)
{
    __shared__ float w[R_REG];
    __shared__ float srep[H_DIM];
    __shared__ float c1s[HH];
    const int tid = threadIdx.x;   // 512 threads

    if (tid == 0) {
        float mx = g_sa[0];
        #pragma unroll
        for (int r = 1; r < R_REG; r++) mx = fmaxf(mx, g_sa[r]);
        float sum = 0.f;
        #pragma unroll
        for (int r = 0; r < R_REG; r++) { w[r] = expf(g_sa[r] - mx); sum += w[r]; }
        const float inv = 1.f / sum;
        #pragma unroll
        for (int r = 0; r < R_REG; r++) w[r] *= inv;
    }
    __syncthreads();

    {
        float a = 0.f;
        #pragma unroll
        for (int r = 0; r < R_REG; r++)
            a += w[r] * g_slide_emb[r * H_DIM + tid];
        srep[tid] = a;
    }
    __syncthreads();

    if (tid < HH) {
        float a = 0.f;
        #pragma unroll 4
        for (int h = 0; h < H_DIM; h++)
            a += srep[h] * Wc1[h * HH + tid];
        c1s[tid] = gelu_f(a + bc1[tid]);
    }
    __syncthreads();

    if (tid < 2) {
        float a = bc2[tid];
        #pragma unroll 4
        for (int j = 0; j < HH; j++)
            a += c1s[j] * Wc2[j * 2 + tid];
        out[tid] = a;
    }
}

// =================================================================================
extern "C" void kernel_launch(void* const* d_in, const int* in_sizes, int n_in,
                              void* d_out, int out_size)
{
    const float* emb  = (const float*)d_in[0];
    const float* W1   = (const float*)d_in[1];
    const float* b1   = (const float*)d_in[2];
    const float* Wa1  = (const float*)d_in[3];
    const float* ba1  = (const float*)d_in[4];
    const float* Wa2  = (const float*)d_in[5];
    const float* ba2  = (const float*)d_in[6];
    const float* Ws   = (const float*)d_in[7];
    const float* bs   = (const float*)d_in[8];
    const float* Wsa1 = (const float*)d_in[9];
    const float* bsa1 = (const float*)d_in[10];
    const float* Wsa2 = (const float*)d_in[11];
    const float* bsa2 = (const float*)d_in[12];
    const float* Wc1  = (const float*)d_in[13];
    const float* bc1  = (const float*)d_in[14];
    const float* Wc2  = (const float*)d_in[15];
    const float* bc2  = (const float*)d_in[16];
    float* out = (float*)d_out;

    k1_gemm_gelu<<<dim3(H_DIM / 128, N_TOK / 128), 256>>>(emb, W1, b1);
    k2_scores<<<N_TOK / 64, 256>>>(Wa1, ba1, Wa2, ba2);
    k3a_region_stats<<<R_REG, 256>>>();
    k3b_weighted_partial<<<dim3(SPLITS, R_REG), 256>>>();
    k3c_reduce_rf<<<R_REG, 512>>>();
    k4a_slide_emb<<<R_REG, 512>>>(Ws, bs);
    k4b_slide_attn<<<R_REG, 256>>>(Wsa1, bsa1, Wsa2, bsa2);
    k4c_classify<<<1, 512>>>(Wc1, bc1, Wc2, bc2, out);
}

// round 9
// speedup vs baseline: 1.0526x; 1.0526x over previous
#include <cuda_runtime.h>
#include <math.h>

// Problem constants
#define N_TOK 65536
#define D_IN  1024
#define H_DIM 512
#define HH    256          // H/2
#define R_REG 16
#define M_PER (N_TOK / R_REG)   // 4096
#define SPLITS 64

// ---------------- static device scratch (no allocations allowed) ----------------
__device__ float g_region_emb[N_TOK * H_DIM];            // 128 MiB
__device__ float g_scores[N_TOK];
__device__ float g_rmax[R_REG];
__device__ float g_rsum[R_REG];
__device__ float g_partial[R_REG * SPLITS * H_DIM];      // 2 MiB
__device__ float g_region_features[R_REG * H_DIM];
__device__ float g_slide_emb[R_REG * H_DIM];
__device__ float g_sa[R_REG];

__device__ __forceinline__ float gelu_f(float x) {
    // exact-erf GELU (matches torch nn.GELU default / jax approximate=False)
    return 0.5f * x * (1.0f + erff(x * 0.70710678118654752440f));
}

// ---------------- packed fp32x2 helpers (Blackwell FFMA2 path) ----------------
// fma.rn.f32x2 = one issue slot, two IEEE fp32 FMAs per lane. ptxas never emits
// this from C++ (SASS_QUICKREF: "FFMA2 ... only via PTX fma.rn.f32x2").
__device__ __forceinline__ unsigned long long pack_dup(float a) {
    unsigned long long r;
    asm("mov.b64 %0, {%1, %1};" : "=l"(r) : "f"(a));
    return r;
}
__device__ __forceinline__ void fma2(unsigned long long& acc,
                                     unsigned long long a, unsigned long long b) {
    asm("fma.rn.f32x2 %0, %1, %2, %0;" : "+l"(acc) : "l"(a), "l"(b));
}
__device__ __forceinline__ float2 unpack2(unsigned long long v) {
    float2 f;
    asm("mov.b64 {%0, %1}, %2;" : "=f"(f.x), "=f"(f.y) : "l"(v));
    return f;
}

// =================================================================================
// K1: region_emb = gelu(E @ W1 + b1)
// E: (65536 x 1024) row-major, W1: (1024 x 512) row-major
// Tile: BM=128, BN=128, BK=16, 256 threads, 8x8 per-thread microtile held as
// 8x4 packed f32x2 accumulators (pair = adjacent output columns).
// =================================================================================
__global__ __launch_bounds__(256, 2)
void k1_gemm_gelu(const float* __restrict__ A, const float* __restrict__ W,
                  const float* __restrict__ bias)
{
    const int BM = 128, BN = 128, BK = 16;
    __shared__ float As[BK][BM];   // transposed A tile: [k][m]
    __shared__ float Bs[BK][BN];   // [k][n]

    const int tid = threadIdx.x;
    const int bx = blockIdx.x;     // column block (0..3)
    const int by = blockIdx.y;     // row block    (0..511)
    const int tr = tid >> 4;       // 0..15 -> rows tr*8 .. tr*8+7
    const int tc = tid & 15;       // 0..15 -> cols tc*4..+3 and tc*4+64..+3

    // A tile: 128x16 = 2048 floats = 2 float4 per thread
    const int lin0 = tid * 4;
    const int lin1 = 1024 + tid * 4;
    const int ar0 = lin0 >> 4, ak0 = lin0 & 15;
    const int ar1 = lin1 >> 4, ak1 = lin1 & 15;
    const float* Ag0 = A + (long)(by * BM + ar0) * D_IN + ak0;
    const float* Ag1 = A + (long)(by * BM + ar1) * D_IN + ak1;

    // B tile: 16x128 = 2048 floats = 2 float4 per thread
    const int br0 = lin0 >> 7, bc0 = lin0 & 127;
    const int br1 = lin1 >> 7, bc1 = lin1 & 127;
    const float* Bg0 = W + (long)br0 * H_DIM + bx * BN + bc0;
    const float* Bg1 = W + (long)br1 * H_DIM + bx * BN + bc1;

    float4 pa0 = *(const float4*)(Ag0);
    float4 pa1 = *(const float4*)(Ag1);
    float4 pb0 = *(const float4*)(Bg0);
    float4 pb1 = *(const float4*)(Bg1);

    // packed accumulators: acc2[i][j] = cols (2j, 2j+1) of this thread's 8-col group
    unsigned long long acc2[8][4];
    #pragma unroll
    for (int i = 0; i < 8; i++)
        #pragma unroll
        for (int j = 0; j < 4; j++) acc2[i][j] = 0ull;

    for (int k0 = 0; k0 < D_IN; k0 += BK) {
        // store prefetched tiles (A transposed, scalar stores)
        As[ak0 + 0][ar0] = pa0.x; As[ak0 + 1][ar0] = pa0.y;
        As[ak0 + 2][ar0] = pa0.z; As[ak0 + 3][ar0] = pa0.w;
        As[ak1 + 0][ar1] = pa1.x; As[ak1 + 1][ar1] = pa1.y;
        As[ak1 + 2][ar1] = pa1.z; As[ak1 + 3][ar1] = pa1.w;
        *(float4*)&Bs[br0][bc0] = pb0;
        *(float4*)&Bs[br1][bc1] = pb1;
        __syncthreads();

        if (k0 + BK < D_IN) {
            pa0 = *(const float4*)(Ag0 + k0 + BK);
            pa1 = *(const float4*)(Ag1 + k0 + BK);
            pb0 = *(const float4*)(Bg0 + (long)(k0 + BK) * H_DIM);
            pb1 = *(const float4*)(Bg1 + (long)(k0 + BK) * H_DIM);
        }

        #pragma unroll
        for (int k = 0; k < BK; k++) {
            float a[8];
            *(float4*)&a[0] = *(const float4*)&As[k][tr * 8];
            *(float4*)&a[4] = *(const float4*)&As[k][tr * 8 + 4];
            float4 bq0 = *(const float4*)&Bs[k][tc * 4];
            float4 bq1 = *(const float4*)&Bs[k][tc * 4 + 64];
            unsigned long long bp[4];
            bp[0] = *(unsigned long long*)&bq0.x;
            bp[1] = *(unsigned long long*)&bq0.z;
            bp[2] = *(unsigned long long*)&bq1.x;
            bp[3] = *(unsigned long long*)&bq1.z;
            #pragma unroll
            for (int i = 0; i < 8; i++) {
                const unsigned long long ap = pack_dup(a[i]);
                #pragma unroll
                for (int j = 0; j < 4; j++)
                    fma2(acc2[i][j], ap, bp[j]);
            }
        }
        __syncthreads();
    }

    // epilogue: bias + gelu, float4 stores
    const int cb = bx * BN + tc * 4;
    float bv[8];
    #pragma unroll
    for (int j = 0; j < 4; j++) { bv[j] = bias[cb + j]; bv[4 + j] = bias[cb + 64 + j]; }

    #pragma unroll
    for (int i = 0; i < 8; i++) {
        const int row = by * BM + tr * 8 + i;
        float* o = g_region_emb + (long)row * H_DIM;
        float2 p0 = unpack2(acc2[i][0]);
        float2 p1 = unpack2(acc2[i][1]);
        float2 p2 = unpack2(acc2[i][2]);
        float2 p3 = unpack2(acc2[i][3]);
        float4 v;
        v.x = gelu_f(p0.x + bv[0]);
        v.y = gelu_f(p0.y + bv[1]);
        v.z = gelu_f(p1.x + bv[2]);
        v.w = gelu_f(p1.y + bv[3]);
        *(float4*)(o + cb) = v;
        v.x = gelu_f(p2.x + bv[4]);
        v.y = gelu_f(p2.y + bv[5]);
        v.z = gelu_f(p3.x + bv[6]);
        v.w = gelu_f(p3.y + bv[7]);
        *(float4*)(o + cb + 64) = v;
    }
}

// =================================================================================
// K2: scores[n] = tanh(region_emb[n,:] @ Wa1 + ba1) @ Wa2 + ba2
// GEMM tile covers the FULL 256-wide Wa1 so the tanh+Wa2 contraction fuses into
// the epilogue (65536x256 intermediate never materialized).
// BM=64, BN=256, BK=16, 256 threads, 8x8 microtile as 8x4 packed f32x2.
// =================================================================================
__global__ __launch_bounds__(256, 2)
void k2_scores(const float* __restrict__ Wa1, const float* __restrict__ ba1,
               const float* __restrict__ Wa2, const float* __restrict__ ba2)
{
    const int BM = 64, BK = 16;
    __shared__ float As[BK][BM];     // transposed
    __shared__ float Bs[BK][256];

    const int tid = threadIdx.x;
    const int bx = blockIdx.x;       // 0..1023 (row block of 64 tokens)
    const int tr = tid >> 5;         // 0..7  (warp id)
    const int tc = tid & 31;         // lane

    // A tile: 64x16 = 1024 floats -> 1 float4/thread
    const int lin = tid * 4;
    const int ar = lin >> 4, ak = lin & 15;
    const float* Ag = g_region_emb + (long)(bx * BM + ar) * H_DIM + ak;

    float4 pa = *(const float4*)Ag;
    float4 pb[4];
    #pragma unroll
    for (int i = 0; i < 4; i++) {
        const int l = i * 1024 + tid * 4;
        pb[i] = *(const float4*)(Wa1 + (long)(l >> 8) * HH + (l & 255));
    }

    unsigned long long acc2[8][4];
    #pragma unroll
    for (int i = 0; i < 8; i++)
        #pragma unroll
        for (int j = 0; j < 4; j++) acc2[i][j] = 0ull;

    for (int k0 = 0; k0 < H_DIM; k0 += BK) {
        As[ak + 0][ar] = pa.x; As[ak + 1][ar] = pa.y;
        As[ak + 2][ar] = pa.z; As[ak + 3][ar] = pa.w;
        #pragma unroll
        for (int i = 0; i < 4; i++) {
            const int l = i * 1024 + tid * 4;
            *(float4*)&Bs[l >> 8][l & 255] = pb[i];
        }
        __syncthreads();

        if (k0 + BK < H_DIM) {
            pa = *(const float4*)(Ag + k0 + BK);
            #pragma unroll
            for (int i = 0; i < 4; i++) {
                const int l = i * 1024 + tid * 4;
                pb[i] = *(const float4*)(Wa1 + (long)((l >> 8) + k0 + BK) * HH + (l & 255));
            }
        }

        #pragma unroll
        for (int k = 0; k < BK; k++) {
            float a[8];
            *(float4*)&a[0] = *(const float4*)&As[k][tr * 8];
            *(float4*)&a[4] = *(const float4*)&As[k][tr * 8 + 4];
            float4 bq0 = *(const float4*)&Bs[k][tc * 4];
            float4 bq1 = *(const float4*)&Bs[k][tc * 4 + 128];
            unsigned long long bp[4];
            bp[0] = *(unsigned long long*)&bq0.x;
            bp[1] = *(unsigned long long*)&bq0.z;
            bp[2] = *(unsigned long long*)&bq1.x;
            bp[3] = *(unsigned long long*)&bq1.z;
            #pragma unroll
            for (int i = 0; i < 8; i++) {
                const unsigned long long ap = pack_dup(a[i]);
                #pragma unroll
                for (int j = 0; j < 4; j++)
                    fma2(acc2[i][j], ap, bp[j]);
            }
        }
        __syncthreads();
    }

    // epilogue: tanh, weight by Wa2, per-row reduce (this thread's 8 cols),
    // then warp shuffle-reduce across the 32 column groups (= lanes).
    const int c0 = tc * 4, c1 = tc * 4 + 128;
    float b1r[8], w2r[8];
    #pragma unroll
    for (int j = 0; j < 4; j++) {
        b1r[j]     = ba1[c0 + j];  w2r[j]     = Wa2[c0 + j];
        b1r[4 + j] = ba1[c1 + j];  w2r[4 + j] = Wa2[c1 + j];
    }

    float p[8];
    #pragma unroll
    for (int i = 0; i < 8; i++) {
        float2 q0 = unpack2(acc2[i][0]);
        float2 q1 = unpack2(acc2[i][1]);
        float2 q2 = unpack2(acc2[i][2]);
        float2 q3 = unpack2(acc2[i][3]);
        float av[8] = { q0.x, q0.y, q1.x, q1.y, q2.x, q2.y, q3.x, q3.y };
        float s = 0.f;
        #pragma unroll
        for (int j = 0; j < 8; j++)
            s += tanhf(av[j] + b1r[j]) * w2r[j];
        p[i] = s;
    }
    #pragma unroll
    for (int off = 16; off > 0; off >>= 1)
        #pragma unroll
        for (int i = 0; i < 8; i++)
            p[i] += __shfl_down_sync(0xffffffffu, p[i], off);

    if (tc == 0) {
        const float bb = ba2[0];
        #pragma unroll
        for (int i = 0; i < 8; i++)
            g_scores[bx * BM + tr * 8 + i] = p[i] + bb;
    }
}

// =================================================================================
// K3a: per-region max and sum(exp(score-max)).  Region r owns tokens m*16 + r.
// =================================================================================
__global__ void k3a_region_stats()
{
    __shared__ float red[256];
    const int r = blockIdx.x, tid = threadIdx.x;

    float mx = -1e30f;
    for (int m = tid; m < M_PER; m += 256)
        mx = fmaxf(mx, g_scores[m * R_REG + r]);
    red[tid] = mx; __syncthreads();
    for (int s = 128; s > 0; s >>= 1) {
        if (tid < s) red[tid] = fmaxf(red[tid], red[tid + s]);
        __syncthreads();
    }
    mx = red[0];
    __syncthreads();

    float sum = 0.f;
    for (int m = tid; m < M_PER; m += 256)
        sum += expf(g_scores[m * R_REG + r] - mx);
    red[tid] = sum; __syncthreads();
    for (int s = 128; s > 0; s >>= 1) {
        if (tid < s) red[tid] += red[tid + s];
        __syncthreads();
    }
    if (tid == 0) { g_rmax[r] = mx; g_rsum[r] = red[0]; }
}

// =================================================================================
// K3b: deterministic split partial weighted sums: each (split,region) block sums
// 64 token rows weighted by exp(score-max). No atomics -> bitwise deterministic.
// =================================================================================
__global__ void k3b_weighted_partial()
{
    const int s = blockIdx.x, r = blockIdx.y, tid = threadIdx.x;
    const float rmax = g_rmax[r];
    const int m0 = s * (M_PER / SPLITS);   // *64
    float a0 = 0.f, a1 = 0.f;
    #pragma unroll 4
    for (int mm = 0; mm < M_PER / SPLITS; mm++) {
        const int n = (m0 + mm) * R_REG + r;
        const float w = expf(g_scores[n] - rmax);
        const float* row = g_region_emb + (long)n * H_DIM;
        a0 += w * row[tid];
        a1 += w * row[tid + 256];
    }
    float* o = g_partial + (long)(r * SPLITS + s) * H_DIM;
    o[tid] = a0; o[tid + 256] = a1;
}

// K3c: reduce partials -> region_features (divide by sumexp)
__global__ void k3c_reduce_rf()
{
    const int r = blockIdx.x, h = threadIdx.x;   // 512 threads
    float a = 0.f;
    for (int s = 0; s < SPLITS; s++)
        a += g_partial[(long)(r * SPLITS + s) * H_DIM + h];
    g_region_features[r * H_DIM + h] = a / g_rsum[r];
}

// =================================================================================
// K4a: slide_emb = gelu(region_features @ Ws + bs)   (16 x 512)
// =================================================================================
__global__ void k4a_slide_emb(const float* __restrict__ Ws, const float* __restrict__ bs)
{
    __shared__ float rf[H_DIM];
    const int r = blockIdx.x, h = threadIdx.x;   // 512 threads
    rf[h] = g_region_features[r * H_DIM + h];
    __syncthreads();
    float a = 0.f;
    #pragma unroll 4
    for (int k = 0; k < H_DIM; k++)
        a += rf[k] * Ws[k * H_DIM + h];
    g_slide_emb[r * H_DIM + h] = gelu_f(a + bs[h]);
}

// K4b: slide attention score per region
__global__ void k4b_slide_attn(const float* __restrict__ Wsa1, const float* __restrict__ bsa1,
                               const float* __restrict__ Wsa2, const float* __restrict__ bsa2)
{
    __shared__ float se[H_DIM];
    __shared__ float red[256];
    const int r = blockIdx.x, j = threadIdx.x;   // 256 threads
    se[j] = g_slide_emb[r * H_DIM + j];
    se[j + 256] = g_slide_emb[r * H_DIM + j + 256];
    __syncthreads();
    float a = 0.f;
    #pragma unroll 4
    for (int h = 0; h < H_DIM; h++)
        a += se[h] * Wsa1[h * HH + j];
    red[j] = tanhf(a + bsa1[j]) * Wsa2[j];
    __syncthreads();
    for (int s = 128; s > 0; s >>= 1) {
        if (j < s) red[j] += red[j + s];
        __syncthreads();
    }
    if (j == 0) g_sa[r] = red[0] + bsa2[0];
}

// K4c: softmax over regions, slide_rep, classifier -> logits
__global__ void k4c_classify(const float* __restrict__ Wc1, const float* __restrict__ bc1,
                             const float* __restrict__ Wc2, const float* __restrict__ bc2,
                             float* __restrict__ out)
{
    __shared__ float w[R_REG];
    __shared__ float srep[H_DIM];
    __shared__ float c1s[HH];
    const int tid = threadIdx.x;   // 512 threads

    if (tid == 0) {
        float mx = g_sa[0];
        #pragma unroll
        for (int r = 1; r < R_REG; r++) mx = fmaxf(mx, g_sa[r]);
        float sum = 0.f;
        #pragma unroll
        for (int r = 0; r < R_REG; r++) { w[r] = expf(g_sa[r] - mx); sum += w[r]; }
        const float inv = 1.f / sum;
        #pragma unroll
        for (int r = 0; r < R_REG; r++) w[r] *= inv;
    }
    __syncthreads();

    {
        float a = 0.f;
        #pragma unroll
        for (int r = 0; r < R_REG; r++)
            a += w[r] * g_slide_emb[r * H_DIM + tid];
        srep[tid] = a;
    }
    __syncthreads();

    if (tid < HH) {
        float a = 0.f;
        #pragma unroll 4
        for (int h = 0; h < H_DIM; h++)
            a += srep[h] * Wc1[h * HH + tid];
        c1s[tid] = gelu_f(a + bc1[tid]);
    }
    __syncthreads();

    if (tid < 2) {
        float a = bc2[tid];
        #pragma unroll 4
        for (int j = 0; j < HH; j++)
            a += c1s[j] * Wc2[j * 2 + tid];
        out[tid] = a;
    }
}

// =================================================================================
extern "C" void kernel_launch(void* const* d_in, const int* in_sizes, int n_in,
                              void* d_out, int out_size)
{
    const float* emb  = (const float*)d_in[0];
    const float* W1   = (const float*)d_in[1];
    const float* b1   = (const float*)d_in[2];
    const float* Wa1  = (const float*)d_in[3];
    const float* ba1  = (const float*)d_in[4];
    const float* Wa2  = (const float*)d_in[5];
    const float* ba2  = (const float*)d_in[6];
    const float* Ws   = (const float*)d_in[7];
    const float* bs   = (const float*)d_in[8];
    const float* Wsa1 = (const float*)d_in[9];
    const float* bsa1 = (const float*)d_in[10];
    const float* Wsa2 = (const float*)d_in[11];
    const float* bsa2 = (const float*)d_in[12];
    const float* Wc1  = (const float*)d_in[13];
    const float* bc1  = (const float*)d_in[14];
    const float* Wc2  = (const float*)d_in[15];
    const float* bc2  = (const float*)d_in[16];
    float* out = (float*)d_out;

    k1_gemm_gelu<<<dim3(H_DIM / 128, N_TOK / 128), 256>>>(emb, W1, b1);
    k2_scores<<<N_TOK / 64, 256>>>(Wa1, ba1, Wa2, ba2);
    k3a_region_stats<<<R_REG, 256>>>();
    k3b_weighted_partial<<<dim3(SPLITS, R_REG), 256>>>();
    k3c_reduce_rf<<<R_REG, 512>>>();
    k4a_slide_emb<<<R_REG, 512>>>(Ws, bs);
    k4b_slide_attn<<<R_REG, 256>>>(Wsa1, bsa1, Wsa2, bsa2);
    k4c_classify<<<1, 512>>>(Wc1, bc1, Wc2, bc2, out);
}

// round 12
// speedup vs baseline: 1.2217x; 1.1607x over previous
#include <cuda_runtime.h>
#include <cuda_bf16.h>
#include <math.h>
#include <stdint.h>

// Problem constants
#define N_TOK 65536
#define D_IN  1024
#define H_DIM 512
#define HH    256          // H/2
#define R_REG 16
#define M_PER (N_TOK / R_REG)   // 4096
#define SPLITS 64

// ---------------- static device scratch (no allocations allowed) ----------------
__device__ float g_region_emb[N_TOK * H_DIM];            // 128 MiB
__device__ float g_scores[N_TOK];
__device__ float g_rmax[R_REG];
__device__ float g_rsum[R_REG];
__device__ float g_partial[R_REG * SPLITS * H_DIM];      // 2 MiB
__device__ float g_region_features[R_REG * H_DIM];
__device__ float g_slide_emb[R_REG * H_DIM];
__device__ float g_sa[R_REG];

__device__ __forceinline__ float gelu_f(float x) {
    // exact-erf GELU (matches torch nn.GELU default / jax approximate=False)
    return 0.5f * x * (1.0f + erff(x * 0.70710678118654752440f));
}

// ---------------- packed fp32x2 helpers (kept for k2) ----------------
__device__ __forceinline__ unsigned long long pack_dup(float a) {
    unsigned long long r;
    asm("mov.b64 %0, {%1, %1};" : "=l"(r) : "f"(a));
    return r;
}
__device__ __forceinline__ void fma2(unsigned long long& acc,
                                     unsigned long long a, unsigned long long b) {
    asm("fma.rn.f32x2 %0, %1, %2, %0;" : "+l"(acc) : "l"(a), "l"(b));
}
__device__ __forceinline__ float2 unpack2(unsigned long long v) {
    float2 f;
    asm("mov.b64 {%0, %1}, %2;" : "=f"(f.x), "=f"(f.y) : "l"(v));
    return f;
}

// ---------------- bf16 split helpers ----------------
__device__ __forceinline__ void split_bf(float x, uint32_t& h, uint32_t& l) {
    __nv_bfloat16 hb = __float2bfloat16_rn(x);
    float r = x - __bfloat162float(hb);   // exact in fp32
    __nv_bfloat16 lb = __float2bfloat16_rn(r);
    h = (uint32_t)(*(uint16_t*)&hb);
    l = (uint32_t)(*(uint16_t*)&lb);
}

// m16n8k16 bf16 MMA, f32 accumulate (sm_80+ mma.sync — valid on plain sm_103)
__device__ __forceinline__ void mma_bf16(float* d, const uint32_t* a, const uint32_t* b) {
    asm volatile(
        "mma.sync.aligned.m16n8k16.row.col.f32.bf16.bf16.f32 "
        "{%0,%1,%2,%3}, {%4,%5,%6,%7}, {%8,%9}, {%0,%1,%2,%3};"
        : "+f"(d[0]), "+f"(d[1]), "+f"(d[2]), "+f"(d[3])
        : "r"(a[0]), "r"(a[1]), "r"(a[2]), "r"(a[3]), "r"(b[0]), "r"(b[1]));
}

// =================================================================================
// K1 (mma.sync bf16-split): region_emb = gelu(E @ W1 + b1)
// E: (65536 x 1024) fp32 row-major, W1: (1024 x 512) fp32 row-major.
// CTA tile 128x128, BK=16, 512 threads = 16 warps laid out 4(m) x 4(n),
// warp tile 32x32 (2 mtiles of m16, 4 ntiles of n8)  -> exactly covers 128x128.
// Each fp32 operand split into bf16 hi+lo; 3 MMAs (hh, hl, lh) per tile.
// SMEM planes: A hi/lo row-major [128 rows][16 k + pad] bf16, 48B row stride;
//              B hi/lo n-major  [128 n   ][16 k + pad] bf16, 48B row stride.
// 12-word row stride => fragment LDS banks (12g+t) all distinct: conflict-free.
// =================================================================================
#define K1_AH 0
#define K1_AL 6144
#define K1_BH 12288
#define K1_BL 18432
#define K1_SMEM 24576

__global__ __launch_bounds__(512, 1)
void k1_mma(const float* __restrict__ A, const float* __restrict__ W,
            const float* __restrict__ bias)
{
    __shared__ __align__(16) unsigned char sm[K1_SMEM];

    const int tid = threadIdx.x;
    const int wid = tid >> 5;
    const int lane = tid & 31;
    const int g = lane >> 2;       // group of 4 (fragment row/col group)
    const int t = lane & 3;        // thread in group
    const int bx = blockIdx.x;     // N block: 0..3  (128 cols each)
    const int by = blockIdx.y;     // M block: 0..511 (128 rows each)

    const int warp_m = (wid & 3) * 32;    // 0,32,64,96
    const int warp_n = (wid >> 2) * 32;   // 0,32,64,96

    // ---- gmem load indices ----
    // A chunk: 128 rows x 16 k = 512 float4; 1 float4/thread
    const int a_row = tid >> 2;          // 0..127
    const int a_q   = tid & 3;           // which float4 in the 16-float row
    const float* Ag = A + (long)(by * 128 + a_row) * D_IN + a_q * 4;
    // B chunk: 16 k x 128 n; thread covers k0..k0+1 for 2 n's
    const int b_k0 = (tid >> 6) * 2;     // 0,2,...,14
    const int b_n  = tid & 63;           // + 64*nj, nj in {0,1}

    const uint32_t* AH = (const uint32_t*)(sm + K1_AH);
    const uint32_t* AL = (const uint32_t*)(sm + K1_AL);
    const uint32_t* BH = (const uint32_t*)(sm + K1_BH);
    const uint32_t* BL = (const uint32_t*)(sm + K1_BL);

    float acc[2][4][4];
    #pragma unroll
    for (int mt = 0; mt < 2; mt++)
        #pragma unroll
        for (int nt = 0; nt < 4; nt++)
            #pragma unroll
            for (int r = 0; r < 4; r++) acc[mt][nt][r] = 0.f;

    // initial prefetch (chunk 0)
    float4 pa = *(const float4*)Ag;
    float pB[2][2];
    #pragma unroll
    for (int nj = 0; nj < 2; nj++) {
        const float* wp = W + (long)b_k0 * H_DIM + bx * 128 + b_n + 64 * nj;
        pB[nj][0] = wp[0];
        pB[nj][1] = wp[H_DIM];
    }

    for (int c = 0; c < D_IN / 16; c++) {
        // ---- store prefetched chunk into split bf16 smem planes ----
        {
            uint32_t h0, h1, h2, h3, l0, l1, l2, l3;
            split_bf(pa.x, h0, l0); split_bf(pa.y, h1, l1);
            split_bf(pa.z, h2, l2); split_bf(pa.w, h3, l3);
            uint2 hv = make_uint2(h0 | (h1 << 16), h2 | (h3 << 16));
            uint2 lv = make_uint2(l0 | (l1 << 16), l2 | (l3 << 16));
            *(uint2*)(sm + K1_AH + a_row * 48 + a_q * 8) = hv;
            *(uint2*)(sm + K1_AL + a_row * 48 + a_q * 8) = lv;
            #pragma unroll
            for (int nj = 0; nj < 2; nj++) {
                uint32_t bh0, bl0, bh1, bl1;
                split_bf(pB[nj][0], bh0, bl0);
                split_bf(pB[nj][1], bh1, bl1);
                const int n = b_n + 64 * nj;
                *(uint32_t*)(sm + K1_BH + n * 48 + b_k0 * 2) = bh0 | (bh1 << 16);
                *(uint32_t*)(sm + K1_BL + n * 48 + b_k0 * 2) = bl0 | (bl1 << 16);
            }
        }
        __syncthreads();

        // ---- prefetch next chunk ----
        if (c + 1 < D_IN / 16) {
            pa = *(const float4*)(Ag + (c + 1) * 16);
            #pragma unroll
            for (int nj = 0; nj < 2; nj++) {
                const float* wp = W + (long)((c + 1) * 16 + b_k0) * H_DIM + bx * 128 + b_n + 64 * nj;
                pB[nj][0] = wp[0];
                pB[nj][1] = wp[H_DIM];
            }
        }

        // ---- fragments + 3-term MMA ----
        uint32_t ah[2][4], al_[2][4];
        #pragma unroll
        for (int mt = 0; mt < 2; mt++) {
            const int r0 = (warp_m + mt * 16 + g) * 12 + t;
            ah[mt][0]  = AH[r0];       ah[mt][1]  = AH[r0 + 96];
            ah[mt][2]  = AH[r0 + 4];   ah[mt][3]  = AH[r0 + 100];
            al_[mt][0] = AL[r0];       al_[mt][1] = AL[r0 + 96];
            al_[mt][2] = AL[r0 + 4];   al_[mt][3] = AL[r0 + 100];
        }
        uint32_t bh[4][2], bl[4][2];
        #pragma unroll
        for (int nt = 0; nt < 4; nt++) {
            const int q0 = (warp_n + nt * 8 + g) * 12 + t;
            bh[nt][0] = BH[q0]; bh[nt][1] = BH[q0 + 4];
            bl[nt][0] = BL[q0]; bl[nt][1] = BL[q0 + 4];
        }
        #pragma unroll
        for (int mt = 0; mt < 2; mt++)
            #pragma unroll
            for (int nt = 0; nt < 4; nt++) {
                mma_bf16(acc[mt][nt], ah[mt],  bh[nt]);
                mma_bf16(acc[mt][nt], ah[mt],  bl[nt]);
                mma_bf16(acc[mt][nt], al_[mt], bh[nt]);
            }
        __syncthreads();
    }

    // ---- epilogue: bias + gelu, float2 stores ----
    #pragma unroll
    for (int mt = 0; mt < 2; mt++) {
        const int row0 = by * 128 + warp_m + mt * 16 + g;
        #pragma unroll
        for (int nt = 0; nt < 4; nt++) {
            const int col = bx * 128 + warp_n + nt * 8 + 2 * t;
            const float2 bb = *(const float2*)(bias + col);
            const float* d = acc[mt][nt];
            float2 v0, v1;
            v0.x = gelu_f(d[0] + bb.x); v0.y = gelu_f(d[1] + bb.y);
            v1.x = gelu_f(d[2] + bb.x); v1.y = gelu_f(d[3] + bb.y);
            *(float2*)(g_region_emb + (long)row0 * H_DIM + col) = v0;
            *(float2*)(g_region_emb + (long)(row0 + 8) * H_DIM + col) = v1;
        }
    }
}

// =================================================================================
// K2: scores[n] = tanh(region_emb[n,:] @ Wa1 + ba1) @ Wa2 + ba2   (unchanged)
// =================================================================================
__global__ __launch_bounds__(256, 2)
void k2_scores(const float* __restrict__ Wa1, const float* __restrict__ ba1,
               const float* __restrict__ Wa2, const float* __restrict__ ba2)
{
    const int BM = 64, BK = 16;
    __shared__ float As[BK][BM];     // transposed
    __shared__ float Bs[BK][256];

    const int tid = threadIdx.x;
    const int bx = blockIdx.x;       // 0..1023 (row block of 64 tokens)
    const int tr = tid >> 5;         // 0..7  (warp id)
    const int tc = tid & 31;         // lane

    const int lin = tid * 4;
    const int ar = lin >> 4, ak = lin & 15;
    const float* Ag = g_region_emb + (long)(bx * BM + ar) * H_DIM + ak;

    float4 pa = *(const float4*)Ag;
    float4 pb[4];
    #pragma unroll
    for (int i = 0; i < 4; i++) {
        const int l = i * 1024 + tid * 4;
        pb[i] = *(const float4*)(Wa1 + (long)(l >> 8) * HH + (l & 255));
    }

    unsigned long long acc2[8][4];
    #pragma unroll
    for (int i = 0; i < 8; i++)
        #pragma unroll
        for (int j = 0; j < 4; j++) acc2[i][j] = 0ull;

    for (int k0 = 0; k0 < H_DIM; k0 += BK) {
        As[ak + 0][ar] = pa.x; As[ak + 1][ar] = pa.y;
        As[ak + 2][ar] = pa.z; As[ak + 3][ar] = pa.w;
        #pragma unroll
        for (int i = 0; i < 4; i++) {
            const int l = i * 1024 + tid * 4;
            *(float4*)&Bs[l >> 8][l & 255] = pb[i];
        }
        __syncthreads();

        if (k0 + BK < H_DIM) {
            pa = *(const float4*)(Ag + k0 + BK);
            #pragma unroll
            for (int i = 0; i < 4; i++) {
                const int l = i * 1024 + tid * 4;
                pb[i] = *(const float4*)(Wa1 + (long)((l >> 8) + k0 + BK) * HH + (l & 255));
            }
        }

        #pragma unroll
        for (int k = 0; k < BK; k++) {
            float a[8];
            *(float4*)&a[0] = *(const float4*)&As[k][tr * 8];
            *(float4*)&a[4] = *(const float4*)&As[k][tr * 8 + 4];
            float4 bq0 = *(const float4*)&Bs[k][tc * 4];
            float4 bq1 = *(const float4*)&Bs[k][tc * 4 + 128];
            unsigned long long bp[4];
            bp[0] = *(unsigned long long*)&bq0.x;
            bp[1] = *(unsigned long long*)&bq0.z;
            bp[2] = *(unsigned long long*)&bq1.x;
            bp[3] = *(unsigned long long*)&bq1.z;
            #pragma unroll
            for (int i = 0; i < 8; i++) {
                const unsigned long long ap = pack_dup(a[i]);
                #pragma unroll
                for (int j = 0; j < 4; j++)
                    fma2(acc2[i][j], ap, bp[j]);
            }
        }
        __syncthreads();
    }

    const int c0 = tc * 4, c1 = tc * 4 + 128;
    float b1r[8], w2r[8];
    #pragma unroll
    for (int j = 0; j < 4; j++) {
        b1r[j]     = ba1[c0 + j];  w2r[j]     = Wa2[c0 + j];
        b1r[4 + j] = ba1[c1 + j];  w2r[4 + j] = Wa2[c1 + j];
    }

    float p[8];
    #pragma unroll
    for (int i = 0; i < 8; i++) {
        float2 q0 = unpack2(acc2[i][0]);
        float2 q1 = unpack2(acc2[i][1]);
        float2 q2 = unpack2(acc2[i][2]);
        float2 q3 = unpack2(acc2[i][3]);
        float av[8] = { q0.x, q0.y, q1.x, q1.y, q2.x, q2.y, q3.x, q3.y };
        float s = 0.f;
        #pragma unroll
        for (int j = 0; j < 8; j++)
            s += tanhf(av[j] + b1r[j]) * w2r[j];
        p[i] = s;
    }
    #pragma unroll
    for (int off = 16; off > 0; off >>= 1)
        #pragma unroll
        for (int i = 0; i < 8; i++)
            p[i] += __shfl_down_sync(0xffffffffu, p[i], off);

    if (tc == 0) {
        const float bb = ba2[0];
        #pragma unroll
        for (int i = 0; i < 8; i++)
            g_scores[bx * BM + tr * 8 + i] = p[i] + bb;
    }
}

// ================================ K3 / K4 (unchanged) ============================
__global__ void k3a_region_stats()
{
    __shared__ float red[256];
    const int r = blockIdx.x, tid = threadIdx.x;

    float mx = -1e30f;
    for (int m = tid; m < M_PER; m += 256)
        mx = fmaxf(mx, g_scores[m * R_REG + r]);
    red[tid] = mx; __syncthreads();
    for (int s = 128; s > 0; s >>= 1) {
        if (tid < s) red[tid] = fmaxf(red[tid], red[tid + s]);
        __syncthreads();
    }
    mx = red[0];
    __syncthreads();

    float sum = 0.f;
    for (int m = tid; m < M_PER; m += 256)
        sum += expf(g_scores[m * R_REG + r] - mx);
    red[tid] = sum; __syncthreads();
    for (int s = 128; s > 0; s >>= 1) {
        if (tid < s) red[tid] += red[tid + s];
        __syncthreads();
    }
    if (tid == 0) { g_rmax[r] = mx; g_rsum[r] = red[0]; }
}

__global__ void k3b_weighted_partial()
{
    const int s = blockIdx.x, r = blockIdx.y, tid = threadIdx.x;
    const float rmax = g_rmax[r];
    const int m0 = s * (M_PER / SPLITS);   // *64
    float a0 = 0.f, a1 = 0.f;
    #pragma unroll 4
    for (int mm = 0; mm < M_PER / SPLITS; mm++) {
        const int n = (m0 + mm) * R_REG + r;
        const float w = expf(g_scores[n] - rmax);
        const float* row = g_region_emb + (long)n * H_DIM;
        a0 += w * row[tid];
        a1 += w * row[tid + 256];
    }
    float* o = g_partial + (long)(r * SPLITS + s) * H_DIM;
    o[tid] = a0; o[tid + 256] = a1;
}

__global__ void k3c_reduce_rf()
{
    const int r = blockIdx.x, h = threadIdx.x;   // 512 threads
    float a = 0.f;
    for (int s = 0; s < SPLITS; s++)
        a += g_partial[(long)(r * SPLITS + s) * H_DIM + h];
    g_region_features[r * H_DIM + h] = a / g_rsum[r];
}

__global__ void k4a_slide_emb(const float* __restrict__ Ws, const float* __restrict__ bs)
{
    __shared__ float rf[H_DIM];
    const int r = blockIdx.x, h = threadIdx.x;   // 512 threads
    rf[h] = g_region_features[r * H_DIM + h];
    __syncthreads();
    float a = 0.f;
    #pragma unroll 4
    for (int k = 0; k < H_DIM; k++)
        a += rf[k] * Ws[k * H_DIM + h];
    g_slide_emb[r * H_DIM + h] = gelu_f(a + bs[h]);
}

__global__ void k4b_slide_attn(const float* __restrict__ Wsa1, const float* __restrict__ bsa1,
                               const float* __restrict__ Wsa2, const float* __restrict__ bsa2)
{
    __shared__ float se[H_DIM];
    __shared__ float red[256];
    const int r = blockIdx.x, j = threadIdx.x;   // 256 threads
    se[j] = g_slide_emb[r * H_DIM + j];
    se[j + 256] = g_slide_emb[r * H_DIM + j + 256];
    __syncthreads();
    float a = 0.f;
    #pragma unroll 4
    for (int h = 0; h < H_DIM; h++)
        a += se[h] * Wsa1[h * HH + j];
    red[j] = tanhf(a + bsa1[j]) * Wsa2[j];
    __syncthreads();
    for (int s = 128; s > 0; s >>= 1) {
        if (j < s) red[j] += red[j + s];
        __syncthreads();
    }
    if (j == 0) g_sa[r] = red[0] + bsa2[0];
}

__global__ void k4c_classify(const float* __restrict__ Wc1, const float* __restrict__ bc1,
                             const float* __restrict__ Wc2, const float* __restrict__ bc2,
                             float* __restrict__ out)
{
    __shared__ float w[R_REG];
    __shared__ float srep[H_DIM];
    __shared__ float c1s[HH];
    const int tid = threadIdx.x;   // 512 threads

    if (tid == 0) {
        float mx = g_sa[0];
        #pragma unroll
        for (int r = 1; r < R_REG; r++) mx = fmaxf(mx, g_sa[r]);
        float sum = 0.f;
        #pragma unroll
        for (int r = 0; r < R_REG; r++) { w[r] = expf(g_sa[r] - mx); sum += w[r]; }
        const float inv = 1.f / sum;
        #pragma unroll
        for (int r = 0; r < R_REG; r++) w[r] *= inv;
    }
    __syncthreads();

    {
        float a = 0.f;
        #pragma unroll
        for (int r = 0; r < R_REG; r++)
            a += w[r] * g_slide_emb[r * H_DIM + tid];
        srep[tid] = a;
    }
    __syncthreads();

    if (tid < HH) {
        float a = 0.f;
        #pragma unroll 4
        for (int h = 0; h < H_DIM; h++)
            a += srep[h] * Wc1[h * HH + tid];
        c1s[tid] = gelu_f(a + bc1[tid]);
    }
    __syncthreads();

    if (tid < 2) {
        float a = bc2[tid];
        #pragma unroll 4
        for (int j = 0; j < HH; j++)
            a += c1s[j] * Wc2[j * 2 + tid];
        out[tid] = a;
    }
}

// =================================================================================
extern "C" void kernel_launch(void* const* d_in, const int* in_sizes, int n_in,
                              void* d_out, int out_size)
{
    const float* emb  = (const float*)d_in[0];
    const float* W1   = (const float*)d_in[1];
    const float* b1   = (const float*)d_in[2];
    const float* Wa1  = (const float*)d_in[3];
    const float* ba1  = (const float*)d_in[4];
    const float* Wa2  = (const float*)d_in[5];
    const float* ba2  = (const float*)d_in[6];
    const float* Ws   = (const float*)d_in[7];
    const float* bs   = (const float*)d_in[8];
    const float* Wsa1 = (const float*)d_in[9];
    const float* bsa1 = (const float*)d_in[10];
    const float* Wsa2 = (const float*)d_in[11];
    const float* bsa2 = (const float*)d_in[12];
    const float* Wc1  = (const float*)d_in[13];
    const float* bc1  = (const float*)d_in[14];
    const float* Wc2  = (const float*)d_in[15];
    const float* bc2  = (const float*)d_in[16];
    float* out = (float*)d_out;

    k1_mma<<<dim3(H_DIM / 128, N_TOK / 128), 512>>>(emb, W1, b1);
    k2_scores<<<N_TOK / 64, 256>>>(Wa1, ba1, Wa2, ba2);
    k3a_region_stats<<<R_REG, 256>>>();
    k3b_weighted_partial<<<dim3(SPLITS, R_REG), 256>>>();
    k3c_reduce_rf<<<R_REG, 512>>>();
    k4a_slide_emb<<<R_REG, 512>>>(Ws, bs);
    k4b_slide_attn<<<R_REG, 256>>>(Wsa1, bsa1, Wsa2, bsa2);
    k4c_classify<<<1, 512>>>(Wc1, bc1, Wc2, bc2, out);
}